// round 1
// baseline (speedup 1.0000x reference)
#include <cuda_runtime.h>

// Problem shape (fixed by dataset): D=1024, P=256, R=64, K=1024
#define D_DIRS 1024
#define P_PTS  256
#define R_RANK 64
#define K_SUB  1024

// Scratch (allocation-free rule: __device__ globals)
__device__ float g_asum[D_DIRS * R_RANK];   // sum over p of attenuation
__device__ float g_bsum[D_DIRS * R_RANK];   // sum over p of radiation
__device__ float g_M[R_RANK * R_RANK];      // M[r1][r2] = sum_d asum[d,r1]*bsum[d,r2]

// ---------------------------------------------------------------------------
// Kernel 1: reduce over P.  One block per (tensor, d).  Block reads a
// contiguous 64 KB slab [P=256][R=64] fp32, fully coalesced float4 loads.
// 2048 blocks x 256 threads; this kernel carries all 128 MiB of HBM traffic.
// ---------------------------------------------------------------------------
__global__ __launch_bounds__(256) void reduce_p_kernel(
    const float* __restrict__ atten, const float* __restrict__ rad)
{
    const int b = blockIdx.x;
    const bool is_b = (b >= D_DIRS);
    const int d = b & (D_DIRS - 1);
    const float* __restrict__ src = is_b ? rad : atten;
    float* __restrict__ dst = is_b ? g_bsum : g_asum;

    const float4* __restrict__ in =
        reinterpret_cast<const float4*>(src) + (size_t)d * (P_PTS * R_RANK / 4);

    const int t = threadIdx.x;
    const int col  = t & 15;   // which float4 within the 64-float row (16 per row)
    const int prow = t >> 4;   // which of 16 rows per sweep

    float4 acc = make_float4(0.f, 0.f, 0.f, 0.f);
    #pragma unroll
    for (int i = 0; i < 16; i++) {
        // address = i*256 + t  -> consecutive threads, consecutive float4s
        float4 v = in[i * 256 + t];
        acc.x += v.x; acc.y += v.y; acc.z += v.z; acc.w += v.w;
    }

    __shared__ float4 s[256];
    s[t] = acc;
    __syncthreads();

    if (t < 16) {
        float4 sum = s[t];
        #pragma unroll
        for (int j = 1; j < 16; j++) {
            float4 v = s[j * 16 + t];
            sum.x += v.x; sum.y += v.y; sum.z += v.z; sum.w += v.w;
        }
        reinterpret_cast<float4*>(dst + d * R_RANK)[t] = sum;
    }
}

// ---------------------------------------------------------------------------
// Kernel 2: M = asum^T @ bsum  (64x64, contraction over D=1024).
// 64 blocks (one per r1) x 256 threads (r2 = t&63, d-phase = t>>6).
// asum/bsum (512 KB total) are L2-resident from kernel 1.
// ---------------------------------------------------------------------------
__global__ __launch_bounds__(256) void make_m_kernel()
{
    const int r1 = blockIdx.x;
    const int t  = threadIdx.x;
    const int r2 = t & 63;
    const int g  = t >> 6;     // 4 d-phases

    float acc = 0.f;
    #pragma unroll 8
    for (int d = g; d < D_DIRS; d += 4) {
        acc += g_asum[d * R_RANK + r1] * g_bsum[d * R_RANK + r2];
    }

    __shared__ float s[256];
    s[t] = acc;
    __syncthreads();
    if (t < 64) {
        g_M[r1 * R_RANK + t] = s[t] + s[64 + t] + s[128 + t] + s[192 + t];
    }
}

// ---------------------------------------------------------------------------
// Kernel 3: csi[k] = (1/D) * f_k^T M f_k.
// 256 blocks x 256 threads; block handles 4 k's, 64 threads (one r2 each) per k.
// F rows staged in smem; M read from L2 (coalesced columns across lanes).
// ---------------------------------------------------------------------------
__global__ __launch_bounds__(256) void quadform_kernel(
    const float* __restrict__ F, float* __restrict__ out)
{
    const int t = threadIdx.x;
    const int klocal = t >> 6;        // 0..3
    const int r2 = t & 63;
    const int k = blockIdx.x * 4 + klocal;

    __shared__ float fsh[4][R_RANK];
    // coalesced load of 4 rows of F
    fsh[klocal][r2] = F[(size_t)k * R_RANK + r2];
    __syncthreads();

    float acc = 0.f;
    #pragma unroll
    for (int r1 = 0; r1 < R_RANK; r1++) {
        acc += fsh[klocal][r1] * g_M[r1 * R_RANK + r2];  // fsh: smem broadcast
    }
    float val = acc * fsh[klocal][r2];

    // reduce 64 values per k: warp-reduce each of the 2 warps, combine in smem
    #pragma unroll
    for (int off = 16; off > 0; off >>= 1)
        val += __shfl_xor_sync(0xffffffffu, val, off);

    __shared__ float partial[8];
    if ((t & 31) == 0) partial[t >> 5] = val;
    __syncthreads();
    if (t < 4) {
        out[blockIdx.x * 4 + t] =
            (partial[2 * t] + partial[2 * t + 1]) * (1.0f / (float)D_DIRS);
    }
}

extern "C" void kernel_launch(void* const* d_in, const int* in_sizes, int n_in,
                              void* d_out, int out_size)
{
    const float* atten = (const float*)d_in[0];   // [D,P,R] fp32
    const float* rad   = (const float*)d_in[1];   // [D,P,R] fp32
    const float* F     = (const float*)d_in[2];   // [K,R]   fp32
    float* out = (float*)d_out;                   // [K]     fp32

    (void)in_sizes; (void)n_in; (void)out_size;

    reduce_p_kernel<<<2 * D_DIRS, 256>>>(atten, rad);
    make_m_kernel<<<R_RANK, 256>>>();
    quadform_kernel<<<K_SUB / 4, 256>>>(F, out);
}